// round 13
// baseline (speedup 1.0000x reference)
#include <cuda_runtime.h>
#include <cuda_bf16.h>
#include <cstdint>

// Problem constants (B=32, C=1 heat, H=W=256, K=500)
#define NB     32
#define WID    256
#define HW     65536
#define KTOP   500
#define NIMG   64
#define CAND_MAX 4096      // pred candidates v>=TAU_PRE (E~1785, sigma~42)
#define SURV   1024        // sort width
#define BINS   4096        // value bins: clamp((int)(v*4096), 0, 4095)

#define RCHUNK 8                 // rows per k_nms block
#define NCHUNK (WID / RCHUNK)    // 32
#define STAGE_MAX 256            // per-block staging (E~55, +27 sigma)
#define TAU_PRE 0.97f            // pred candidate prefilter (rank500 ~0.9921)

#define GSL    16                // gt slices per image
#define SLPX4  (HW / 4 / GSL)    // 1024 float4 per slice
#define TAU_G  0.9896f           // gt prefilter: E~682 in [500,1024] at 7/13 sigma

// Scratch (static device globals — zero-init; consumers reset what they use)
__device__ unsigned long long g_cand[NB][CAND_MAX];     // pred candidates
__device__ int      g_cnt[NB];
__device__ unsigned long long g_gtkeys[NB][SURV];       // gt survivors
__device__ int      g_gtcnt[NB];
__device__ float    g_xs[NIMG][KTOP];
__device__ float    g_ys[NIMG][KTOP];
__device__ double   g_sum;
__device__ int      g_tot;
__device__ unsigned g_ticket;

// per-coordinate assembly tables (see reference _assemble)
__constant__ int   c_whA[10] = {-1,-1, 0, 1, 2, 3, 4, 5, 6, 7};   // m==1
__constant__ int   c_whB[10] = {-1,-1,-1, 9, 8,-1,-1, 9, 8,-1};   // m==0
__constant__ float c_sgn[10] = {0,0,0,-0.5f,0.5f,0,0,0.5f,-0.5f,0};

__device__ __forceinline__ int val_bin(float v) {
    int b = (int)(v * 4096.0f);
    if (b < 0) b = 0;
    if (b > BINS - 1) b = BINS - 1;
    return b;   // monotone non-decreasing in v
}
__device__ __forceinline__ unsigned long long uomin(unsigned long long a, unsigned long long b) { return a < b ? a : b; }
__device__ __forceinline__ unsigned long long uomax(unsigned long long a, unsigned long long b) { return a > b ? a : b; }
__device__ __forceinline__ float max3f(float a, float b, float c) { return fmaxf(a, fmaxf(b, c)); }

// bitonic sort ascending over 1024 smem keys; shuffle stages for j<=16.
// asc key ((~fbits)<<32 | idx) == lax.top_k order (value desc, idx asc).
__device__ __forceinline__ void bitonic1024(unsigned long long* keys, int tid) {
    {
        unsigned long long kv = keys[tid];
        #pragma unroll
        for (unsigned kk = 2; kk <= 32; kk <<= 1) {
            bool up = ((tid & kk) == 0);
            #pragma unroll
            for (unsigned j = kk >> 1; j >= 1; j >>= 1) {
                unsigned long long pv = __shfl_xor_sync(0xffffffffu, kv, j);
                bool keepmin = (((tid & j) == 0) == up);
                kv = keepmin ? uomin(kv, pv) : uomax(kv, pv);
            }
        }
        keys[tid] = kv;
    }
    __syncthreads();
    for (unsigned kk = 64; kk <= SURV; kk <<= 1) {
        bool up = ((tid & kk) == 0);
        for (unsigned j = kk >> 1; j >= 32; j >>= 1) {
            unsigned ixj = tid ^ j;
            if (ixj > tid) {
                unsigned long long a = keys[tid], b = keys[ixj];
                if ((a > b) == up) { keys[tid] = b; keys[ixj] = a; }
            }
            __syncthreads();
        }
        unsigned long long kv = keys[tid];
        #pragma unroll
        for (unsigned j = 16; j >= 1; j >>= 1) {
            unsigned long long pv = __shfl_xor_sync(0xffffffffu, kv, j);
            bool keepmin = (((tid & j) == 0) == up);
            kv = keepmin ? uomin(kv, pv) : uomax(kv, pv);
        }
        keys[tid] = kv;
        __syncthreads();
    }
}

// suffix-scan over 4096 smem bins: smallest bin with suffix-count >= KTOP.
__device__ __forceinline__ int compute_bstar(const int* hist, int* psum,
                                             int* wsuf, int* s_bstar, int tid) {
    int lane = tid & 31, warp = tid >> 5;
    int gv = hist[4*tid] + hist[4*tid+1] + hist[4*tid+2] + hist[4*tid+3];
    int v = gv;
    #pragma unroll
    for (int off = 1; off < 32; off <<= 1) {
        int t2 = __shfl_down_sync(0xffffffffu, v, off);
        if (lane + off < 32) v += t2;
    }
    if (lane == 0) wsuf[warp] = v;
    __syncthreads();
    if (warp == 0) {
        int t = wsuf[lane];
        #pragma unroll
        for (int off = 1; off < 32; off <<= 1) {
            int t2 = __shfl_down_sync(0xffffffffu, t, off);
            if (lane + off < 32) t += t2;
        }
        wsuf[lane] = t;
    }
    __syncthreads();
    int suffix = v + ((warp < 31) ? wsuf[warp + 1] : 0);
    psum[tid] = suffix;
    __syncthreads();
    int above = (tid < 1023) ? psum[tid + 1] : 0;
    if (psum[tid] >= KTOP && above < KTOP) {
        int c = above;
        int bstar = 4 * tid;
        for (int b = 4 * tid + 3; b >= 4 * tid; --b) {
            c += hist[b];
            if (c >= KTOP) { bstar = b; break; }
        }
        *s_bstar = bstar;
    }
    __syncthreads();
    return *s_bstar;
}

// ---------------------------------------------------------------------------
// 3x3 NMS on PRED heatmaps only (reference NMS-es pred_hm, not gt_hm).
// One block per (image, 8-row chunk). Candidate prefilter v >= TAU_PRE lets
// 98.9% of warp-rows skip the window max and append entirely (ballot gate).
// Pixel survives iff v >= max of 3x3 window (window includes v => exactly
// hmax==heat; v>0 implied by TAU_PRE>0).
__global__ void __launch_bounds__(WID) k_nms(const float* __restrict__ pred_hm) {
    __shared__ float rows[RCHUNK + 2][WID];              // 10 KB
    __shared__ unsigned long long stage[STAGE_MAX];      // 2 KB
    __shared__ int s_cnt, s_base;

    int img   = blockIdx.x >> 5;            // / NCHUNK
    int chunk = blockIdx.x & (NCHUNK - 1);
    int y0 = chunk * RCHUNK;
    const float* hm = pred_hm + (size_t)img * HW;
    int x = threadIdx.x;
    int lane = x & 31;

    #pragma unroll
    for (int r = 0; r < RCHUNK + 2; r++) {
        int y = y0 - 1 + r;
        rows[r][x] = (y >= 0 && y < WID) ? __ldg(&hm[y * WID + x]) : -1.0f;
    }
    if (x == 0) s_cnt = 0;
    __syncthreads();

    #pragma unroll
    for (int r = 1; r <= RCHUNK; r++) {
        float v = rows[r][x];
        bool cand = (v >= TAU_PRE);
        if (__ballot_sync(0xffffffffu, cand)) {   // warp-uniform skip
            bool ok = false;
            if (cand) {
                float m = max3f(rows[r-1][x], rows[r][x], rows[r+1][x]);
                if (x > 0)
                    m = fmaxf(m, max3f(rows[r-1][x-1], rows[r][x-1], rows[r+1][x-1]));
                if (x < WID - 1)
                    m = fmaxf(m, max3f(rows[r-1][x+1], rows[r][x+1], rows[r+1][x+1]));
                ok = (v >= m);
            }
            unsigned ballot = __ballot_sync(0xffffffffu, ok);
            if (ok) {
                int leader = __ffs(ballot) - 1;
                int base = 0;
                if (lane == leader) base = atomicAdd(&s_cnt, __popc(ballot));
                base = __shfl_sync(ballot, base, leader);
                int slot = base + __popc(ballot & ((1u << lane) - 1u));
                if (slot < STAGE_MAX) {
                    unsigned fb = __float_as_uint(v);
                    stage[slot] = ((unsigned long long)(~fb) << 32)
                                | (unsigned)((y0 - 1 + r) * WID + x);
                }
            }
        }
    }
    __syncthreads();

    int cnt = s_cnt; if (cnt > STAGE_MAX) cnt = STAGE_MAX;
    if (x == 0) s_base = atomicAdd(&g_cnt[img], cnt);
    __syncthreads();
    int base = s_base;
    for (int i = x; i < cnt; i += WID) {
        int slot = base + i;
        if (slot < CAND_MAX) g_cand[img][slot] = stage[i];
    }
}

// ---------------------------------------------------------------------------
// PRED exact ordered top-500 (one CTA per image, candidates from k_nms).
// Histogram + suffix-scan + prune over ~1780 candidates, then bitonic sort.
// Exactness: g_cand holds ALL NMS survivors >= TAU_PRE; with >=500 stored,
// bstar lands >= bin(TAU_PRE), so every key with bin >= bstar is present.
__global__ void __launch_bounds__(1024) k_sel_pred() {
    __shared__ int hist[BINS];                  // 16 KB
    __shared__ unsigned long long keys[SURV];   // 8 KB
    __shared__ int psum[1024];                  // 4 KB
    __shared__ int wsuf[32];
    __shared__ int s_bstar, s_nsurv;

    int img = blockIdx.x;
    int tid = threadIdx.x;
    int lane = tid & 31;
    int n = g_cnt[img]; if (n > CAND_MAX) n = CAND_MAX;

    for (int i = tid; i < BINS; i += 1024) hist[i] = 0;
    if (tid == 0) { s_bstar = 0; s_nsurv = 0; }
    __syncthreads();

    for (int i = tid; i < n; i += 1024) {
        float v = __uint_as_float(~(unsigned)(g_cand[img][i] >> 32));
        atomicAdd(&hist[val_bin(v)], 1);
    }
    __syncthreads();

    int bstar = compute_bstar(hist, psum, wsuf, &s_bstar, tid);

    int n_pad = (n + 1023) & ~1023;
    for (int i = tid; i < n_pad; i += 1024) {
        unsigned long long key = 0; bool pass = false;
        if (i < n) {
            key = g_cand[img][i];
            float vv = __uint_as_float(~(unsigned)(key >> 32));
            pass = (val_bin(vv) >= bstar);
        }
        unsigned ballot = __ballot_sync(0xffffffffu, pass);
        if (pass) {
            int leader = __ffs(ballot) - 1;
            int base = 0;
            if (lane == leader) base = atomicAdd(&s_nsurv, __popc(ballot));
            base = __shfl_sync(ballot, base, leader);
            int slot = base + __popc(ballot & ((1u << lane) - 1u));
            if (slot < SURV) keys[slot] = key;
        }
    }
    __syncthreads();
    int ns = s_nsurv; if (ns > SURV) ns = SURV;
    if (tid >= ns) keys[tid] = 0xFFFFFFFFFFFFFFFFULL;
    __syncthreads();

    bitonic1024(keys, tid);

    if (tid < KTOP) {
        unsigned p = (unsigned)(keys[tid] & 0xFFFFFFFFULL);
        g_xs[img][tid] = (float)(p & (WID - 1));
        g_ys[img][tid] = (float)(p >> 8);
    }
    if (tid == 0) g_cnt[img] = 0;   // reset for next graph replay
}

// ---------------------------------------------------------------------------
// GT phase 1: filter v >= TAU_G into per-image global lists. 512 CTAs stream
// the 8 MB; survivors E~682 per image (in [500,1024] at 7/13 sigma).
__global__ void __launch_bounds__(256) k_gt_collect(const float* __restrict__ gt_hm) {
    int blk = blockIdx.x;
    int img = blk >> 4, sl = blk & (GSL - 1);
    const float4* hm4 = reinterpret_cast<const float4*>(gt_hm + (size_t)img * HW)
                      + sl * SLPX4;
    int tid = threadIdx.x;
    int lane = tid & 31;
    int pix0 = (sl * SLPX4) * 4;

    #pragma unroll
    for (int i = tid; i < SLPX4; i += 256) {
        float4 v4 = __ldg(&hm4[i]);
        float vv[4] = {v4.x, v4.y, v4.z, v4.w};
        #pragma unroll
        for (int comp = 0; comp < 4; comp++) {
            bool keep = (vv[comp] >= TAU_G);
            unsigned ballot = __ballot_sync(0xffffffffu, keep);
            if (keep) {
                int leader = __ffs(ballot) - 1;
                int base = 0;
                if (lane == leader) base = atomicAdd(&g_gtcnt[img], __popc(ballot));
                base = __shfl_sync(ballot, base, leader);
                int slot = base + __popc(ballot & ((1u << lane) - 1u));
                if (slot < SURV) {
                    unsigned fb = __float_as_uint(vv[comp]);
                    g_gtkeys[img][slot] = ((unsigned long long)(~fb) << 32)
                                        | (unsigned)(pix0 + 4 * i + comp);
                }
            }
        }
    }
}

// GT phase 2: sort survivors -> ranks (reference top_k on RAW gt_hm, no NMS).
// Fast path requires 500 <= cnt <= 1024 (then top-500 subset of survivors).
// Fallback (never in practice): full histogram method over the whole image.
__global__ void __launch_bounds__(1024) k_gt_sort(const float* __restrict__ gt_hm) {
    __shared__ int hist[BINS];                  // 16 KB (fallback only)
    __shared__ unsigned long long keys[SURV];   // 8 KB
    __shared__ int psum[1024];                  // 4 KB
    __shared__ int wsuf[32];
    __shared__ int s_bstar, s_nsurv;

    int img = blockIdx.x;
    int tid = threadIdx.x;
    int lane = tid & 31;
    int cnt = g_gtcnt[img];

    if (cnt >= KTOP && cnt <= SURV) {
        keys[tid] = (tid < cnt) ? g_gtkeys[img][tid] : 0xFFFFFFFFFFFFFFFFULL;
        __syncthreads();
    } else {
        // exact fallback: histogram + prune over the full image
        const float4* hm4 = reinterpret_cast<const float4*>(gt_hm + (size_t)img * HW);
        for (int i = tid; i < BINS; i += 1024) hist[i] = 0;
        if (tid == 0) { s_bstar = 0; s_nsurv = 0; }
        __syncthreads();
        for (int i = tid; i < HW / 4; i += 1024) {
            float4 v = __ldg(&hm4[i]);
            atomicAdd(&hist[val_bin(v.x)], 1);
            atomicAdd(&hist[val_bin(v.y)], 1);
            atomicAdd(&hist[val_bin(v.z)], 1);
            atomicAdd(&hist[val_bin(v.w)], 1);
        }
        __syncthreads();
        int bstar = compute_bstar(hist, psum, wsuf, &s_bstar, tid);
        for (int i = tid; i < HW / 4; i += 1024) {
            float4 v4 = __ldg(&hm4[i]);
            float vv[4] = {v4.x, v4.y, v4.z, v4.w};
            #pragma unroll
            for (int comp = 0; comp < 4; comp++) {
                bool pass = (val_bin(vv[comp]) >= bstar);
                unsigned ballot = __ballot_sync(0xffffffffu, pass);
                if (pass) {
                    int leader = __ffs(ballot) - 1;
                    int base = 0;
                    if (lane == leader) base = atomicAdd(&s_nsurv, __popc(ballot));
                    base = __shfl_sync(ballot, base, leader);
                    int slot = base + __popc(ballot & ((1u << lane) - 1u));
                    if (slot < SURV) {
                        unsigned fb = __float_as_uint(vv[comp]);
                        keys[slot] = ((unsigned long long)(~fb) << 32)
                                   | (unsigned)(4 * i + comp);
                    }
                }
            }
        }
        __syncthreads();
        int ns = s_nsurv; if (ns > SURV) ns = SURV;
        if (tid >= ns) keys[tid] = 0xFFFFFFFFFFFFFFFFULL;
        __syncthreads();
    }

    bitonic1024(keys, tid);

    if (tid < KTOP) {
        unsigned p = (unsigned)(keys[tid] & 0xFFFFFFFFULL);
        g_xs[NB + img][tid] = (float)(p & (WID - 1));
        g_ys[NB + img][tid] = (float)(p >> 8);
    }
    if (tid == 0) g_gtcnt[img] = 0;   // reset for next graph replay
}

// ---------------------------------------------------------------------------
// Loss (R8 version, measured 9.86us): one thread per (item, coordinate);
// mask gates the gathers (halves traffic; loads within branch independent).
#define LOSS_TPB 1024
#define LOSS_N   (NB * KTOP * 10)
__global__ void __launch_bounds__(LOSS_TPB)
k_loss(const float* __restrict__ pred_wh, const float* __restrict__ pred_reg,
       const float* __restrict__ pred_cls,
       const float* __restrict__ gt_wh, const float* __restrict__ gt_reg,
       const float* __restrict__ gt_cls,
       const int* __restrict__ gt_ind, const int* __restrict__ gt_mask,
       float* __restrict__ out) {
    int gidx = blockIdx.x * LOSS_TPB + threadIdx.x;
    float lsum = 0.f;
    int lcnt = 0;
    if (gidx < LOSS_N) {
        int t = gidx / 10;
        int c = gidx - t * 10;
        if (__ldg(&gt_mask[t]) != 0) {
            lcnt = 1;
            int b = t / KTOP;
            int k = t - b * KTOP;
            int ind = __ldg(&gt_ind[t]);
            bool odd = (c & 1);
            int iA = c_whA[c], iB = c_whB[c];
            float sg = c_sgn[c];
            float base, gbase;
            if (odd) {
                base  = g_ys[b][k]      + __ldg(&pred_reg[(size_t)(b * 2 + 1) * HW + ind]);
                gbase = g_ys[NB + b][k] + __ldg(&gt_reg[2 * t + 1]);
            } else {
                base  = g_xs[b][k]      + __ldg(&pred_reg[(size_t)(b * 2) * HW + ind]);
                gbase = g_xs[NB + b][k] + __ldg(&gt_reg[2 * t]);
            }
            bool m  = __ldg(&pred_cls[(size_t)b * HW + ind]) > 0.8f;
            bool gm = __ldg(&gt_cls[t]) > 0.8f;
            float pp = base, tt = gbase;
            // m exactly 0/1 in reference => branch == blend bit-exactly
            if (m) { if (iA >= 0) pp += __ldg(&pred_wh[((size_t)b * 10 + iA) * HW + ind]); }
            else   { if (iB >= 0) pp += sg * __ldg(&pred_wh[((size_t)b * 10 + iB) * HW + ind]); }
            if (gm) { if (iA >= 0) tt += __ldg(&gt_wh[10 * t + iA]); }
            else    { if (iB >= 0) tt += sg * __ldg(&gt_wh[10 * t + iB]); }
            float d = fabsf(pp - tt);
            lsum = (d < 1.f) ? 0.5f * d * d : (d - 0.5f);
        }
    }
    #pragma unroll
    for (int off = 16; off > 0; off >>= 1) {
        lsum += __shfl_down_sync(0xffffffffu, lsum, off);
        lcnt += __shfl_down_sync(0xffffffffu, lcnt, off);
    }
    __shared__ float wsum[LOSS_TPB / 32];
    __shared__ int   wcnt[LOSS_TPB / 32];
    int warp = threadIdx.x >> 5, lane = threadIdx.x & 31;
    if (lane == 0) { wsum[warp] = lsum; wcnt[warp] = lcnt; }
    __syncthreads();
    if (warp == 0) {
        float s = (lane < LOSS_TPB / 32) ? wsum[lane] : 0.f;
        int   cc = (lane < LOSS_TPB / 32) ? wcnt[lane] : 0;
        #pragma unroll
        for (int off = 16; off > 0; off >>= 1) {
            s  += __shfl_down_sync(0xffffffffu, s, off);
            cc += __shfl_down_sync(0xffffffffu, cc, off);
        }
        if (lane == 0) {
            atomicAdd(&g_sum, (double)s);
            atomicAdd(&g_tot, cc);
            __threadfence();
            unsigned ticket = atomicAdd(&g_ticket, 1u);
            if (ticket == gridDim.x - 1) {   // last block: finalize + reset
                double fs = g_sum;
                int tot = g_tot;
                float loss = 0.f;
                if (tot > 0) loss = (float)(fs / (double)(tot < 1 ? 1 : tot));
                out[0] = loss;
                g_sum = 0.0; g_tot = 0; g_ticket = 0u;
            }
        }
    }
}

// ---------------------------------------------------------------------------
extern "C" void kernel_launch(void* const* d_in, const int* in_sizes, int n_in,
                              void* d_out, int out_size) {
    const float* pred_hm  = (const float*)d_in[0];
    const float* pred_wh  = (const float*)d_in[1];
    const float* pred_reg = (const float*)d_in[2];
    const float* pred_cls = (const float*)d_in[3];
    const float* gt_hm    = (const float*)d_in[4];
    const float* gt_wh    = (const float*)d_in[5];
    const float* gt_reg   = (const float*)d_in[6];
    const float* gt_cls   = (const float*)d_in[7];
    const int*   gt_ind   = (const int*)d_in[8];
    const int*   gt_mask  = (const int*)d_in[9];
    float* out = (float*)d_out;

    // side stream for the gt branch; created once on the first (non-captured)
    // correctness call; fork/join via events -> two parallel graph branches.
    static cudaStream_t s2 = nullptr;
    static cudaEvent_t evFork = nullptr, evJoin = nullptr;
    if (s2 == nullptr) {
        cudaStreamCreateWithFlags(&s2, cudaStreamNonBlocking);
        cudaEventCreateWithFlags(&evFork, cudaEventDisableTiming);
        cudaEventCreateWithFlags(&evJoin, cudaEventDisableTiming);
    }

    cudaEventRecord(evFork, 0);
    cudaStreamWaitEvent(s2, evFork, 0);
    k_gt_collect<<<NB * GSL, 256, 0, s2>>>(gt_hm);    // gt branch
    k_gt_sort<<<NB, 1024, 0, s2>>>(gt_hm);
    cudaEventRecord(evJoin, s2);

    k_nms<<<NB * NCHUNK, WID>>>(pred_hm);             // pred branch
    k_sel_pred<<<NB, 1024>>>();

    cudaStreamWaitEvent(0, evJoin, 0);
    k_loss<<<(LOSS_N + LOSS_TPB - 1) / LOSS_TPB, LOSS_TPB>>>(
        pred_wh, pred_reg, pred_cls, gt_wh, gt_reg, gt_cls, gt_ind, gt_mask, out);
}

// round 14
// speedup vs baseline: 1.2094x; 1.2094x over previous
#include <cuda_runtime.h>
#include <cuda_bf16.h>
#include <cstdint>

// Problem constants (B=32, C=1 heat, H=W=256, K=500)
#define NB     32
#define WID    256
#define HW     65536
#define KTOP   500
#define NIMG   64
#define SURV   1024        // sort width / survivor cap
#define BINS   4096        // value bins (fallback only)

#define RCHUNK 8                 // rows per nms block
#define NCHUNK (WID / RCHUNK)    // 32
#define NMS_BLOCKS (NB * NCHUNK) // 1024
#define STAGE_MAX 256            // per-block staging (E~23, huge margin)
#define TAU_P  0.988f            // pred NMS-survivor prefilter: E~750 in [500,1024]
                                 // (rank-500 survivor value ~0.99212)

#define GSL    16                // gt slices per image
#define GT_BLOCKS (NB * GSL)     // 512
#define SLPX4  (HW / 4 / GSL)    // 1024 float4 per slice
#define TAU_G  0.9896f           // gt prefilter: E~682 in [500,1024]

// Scratch (static device globals — zero-init; consumers reset what they use)
__device__ unsigned long long g_cand[NB][SURV];     // pred NMS survivors >= TAU_P
__device__ int      g_cnt[NB];
__device__ unsigned long long g_gtkeys[NB][SURV];   // gt pixels >= TAU_G
__device__ int      g_gtcnt[NB];
__device__ float    g_xs[NIMG][KTOP];
__device__ float    g_ys[NIMG][KTOP];
__device__ double   g_sum;
__device__ int      g_tot;
__device__ unsigned g_ticket;

// per-coordinate assembly tables (see reference _assemble)
__constant__ int   c_whA[10] = {-1,-1, 0, 1, 2, 3, 4, 5, 6, 7};   // m==1
__constant__ int   c_whB[10] = {-1,-1,-1, 9, 8,-1,-1, 9, 8,-1};   // m==0
__constant__ float c_sgn[10] = {0,0,0,-0.5f,0.5f,0,0,0.5f,-0.5f,0};

__device__ __forceinline__ int val_bin(float v) {
    int b = (int)(v * 4096.0f);
    if (b < 0) b = 0;
    if (b > BINS - 1) b = BINS - 1;
    return b;
}
__device__ __forceinline__ unsigned long long uomin(unsigned long long a, unsigned long long b) { return a < b ? a : b; }
__device__ __forceinline__ unsigned long long uomax(unsigned long long a, unsigned long long b) { return a > b ? a : b; }
__device__ __forceinline__ float max3f(float a, float b, float c) { return fmaxf(a, fmaxf(b, c)); }

// key = (~fbits << 32) | idx  => ascending 64-bit sort == lax.top_k order
// (value desc, index asc).
__device__ __forceinline__ unsigned long long mkkey(float v, unsigned idx) {
    return ((unsigned long long)(~__float_as_uint(v)) << 32) | idx;
}

// warp-aggregated append (1 atomic per warp) into a counter+list
__device__ __forceinline__ void wappend_g(bool ok, unsigned long long key,
                                          int* cnt, unsigned long long* buf, int cap) {
    int lane = threadIdx.x & 31;
    unsigned ballot = __ballot_sync(0xffffffffu, ok);
    if (ok) {
        int leader = __ffs(ballot) - 1;
        int base = 0;
        if (lane == leader) base = atomicAdd(cnt, __popc(ballot));
        base = __shfl_sync(ballot, base, leader);
        int slot = base + __popc(ballot & ((1u << lane) - 1u));
        if (slot < cap) buf[slot] = key;
    }
}

// bitonic sort ascending over 1024 smem keys; shuffle stages for j<=16.
__device__ __forceinline__ void bitonic1024(unsigned long long* keys, int tid) {
    {
        unsigned long long kv = keys[tid];
        #pragma unroll
        for (unsigned kk = 2; kk <= 32; kk <<= 1) {
            bool up = ((tid & kk) == 0);
            #pragma unroll
            for (unsigned j = kk >> 1; j >= 1; j >>= 1) {
                unsigned long long pv = __shfl_xor_sync(0xffffffffu, kv, j);
                bool keepmin = (((tid & j) == 0) == up);
                kv = keepmin ? uomin(kv, pv) : uomax(kv, pv);
            }
        }
        keys[tid] = kv;
    }
    __syncthreads();
    for (unsigned kk = 64; kk <= SURV; kk <<= 1) {
        bool up = ((tid & kk) == 0);
        for (unsigned j = kk >> 1; j >= 32; j >>= 1) {
            unsigned ixj = tid ^ j;
            if (ixj > tid) {
                unsigned long long a = keys[tid], b = keys[ixj];
                if ((a > b) == up) { keys[tid] = b; keys[ixj] = a; }
            }
            __syncthreads();
        }
        unsigned long long kv = keys[tid];
        #pragma unroll
        for (unsigned j = 16; j >= 1; j >>= 1) {
            unsigned long long pv = __shfl_xor_sync(0xffffffffu, kv, j);
            bool keepmin = (((tid & j) == 0) == up);
            kv = keepmin ? uomin(kv, pv) : uomax(kv, pv);
        }
        keys[tid] = kv;
        __syncthreads();
    }
}

// suffix-scan over 4096 smem bins (fallback only)
__device__ __forceinline__ int compute_bstar(const int* hist, int* psum,
                                             int* wsuf, int* s_bstar, int tid) {
    int lane = tid & 31, warp = tid >> 5;
    int gv = hist[4*tid] + hist[4*tid+1] + hist[4*tid+2] + hist[4*tid+3];
    int v = gv;
    #pragma unroll
    for (int off = 1; off < 32; off <<= 1) {
        int t2 = __shfl_down_sync(0xffffffffu, v, off);
        if (lane + off < 32) v += t2;
    }
    if (lane == 0) wsuf[warp] = v;
    __syncthreads();
    if (warp == 0) {
        int t = wsuf[lane];
        #pragma unroll
        for (int off = 1; off < 32; off <<= 1) {
            int t2 = __shfl_down_sync(0xffffffffu, t, off);
            if (lane + off < 32) t += t2;
        }
        wsuf[lane] = t;
    }
    __syncthreads();
    int suffix = v + ((warp < 31) ? wsuf[warp + 1] : 0);
    psum[tid] = suffix;
    __syncthreads();
    int above = (tid < 1023) ? psum[tid + 1] : 0;
    if (psum[tid] >= KTOP && above < KTOP) {
        int c = above;
        int bstar = 4 * tid;
        for (int b = 4 * tid + 3; b >= 4 * tid; --b) {
            c += hist[b];
            if (c >= KTOP) { bstar = b; break; }
        }
        *s_bstar = bstar;
    }
    __syncthreads();
    return *s_bstar;
}

// full-accuracy NMS test straight from gmem (fallback only)
__device__ __forceinline__ bool nms_ok_g(const float* hm, int y, int x, float v) {
    if (v <= 0.f) return false;
    #pragma unroll
    for (int dy = -1; dy <= 1; dy++) {
        int ny = y + dy;
        if (ny < 0 || ny >= WID) continue;
        #pragma unroll
        for (int dx = -1; dx <= 1; dx++) {
            if (dy == 0 && dx == 0) continue;
            int nx = x + dx;
            if (nx < 0 || nx >= WID) continue;
            if (__ldg(&hm[ny * WID + nx]) > v) return false;
        }
    }
    return true;
}

// ---------------------------------------------------------------------------
// SCAN kernel: blocks [0, 1024) = pred 3x3 NMS chunks; blocks [1024, 1536) =
// gt threshold-collect slices. Both paths stream concurrently across the grid.
// Pred: pixel kept iff v >= TAU_P and v >= max of its 3x3 window (window
// includes v => exactly hmax==heat; v>0 implied). Reference NMS-es pred only.
// GT: reference top_k's the RAW gt heatmap, so collection is a pure threshold.
__global__ void __launch_bounds__(WID) k_scan(const float* __restrict__ pred_hm,
                                              const float* __restrict__ gt_hm) {
    __shared__ float rows[RCHUNK + 2][WID];              // 10 KB (pred only)
    __shared__ unsigned long long stage[STAGE_MAX];      // 2 KB
    __shared__ int s_cnt, s_base;

    int x = threadIdx.x;
    int lane = x & 31;

    if (blockIdx.x < NMS_BLOCKS) {
        // ---- pred NMS path ----
        int img   = blockIdx.x >> 5;
        int chunk = blockIdx.x & (NCHUNK - 1);
        int y0 = chunk * RCHUNK;
        const float* hm = pred_hm + (size_t)img * HW;

        #pragma unroll
        for (int r = 0; r < RCHUNK + 2; r++) {
            int y = y0 - 1 + r;
            rows[r][x] = (y >= 0 && y < WID) ? __ldg(&hm[y * WID + x]) : -1.0f;
        }
        if (x == 0) s_cnt = 0;
        __syncthreads();

        #pragma unroll
        for (int r = 1; r <= RCHUNK; r++) {
            float v = rows[r][x];
            bool cand = (v >= TAU_P);
            if (__ballot_sync(0xffffffffu, cand)) {   // warp-uniform skip
                bool ok = false;
                if (cand) {
                    float m = max3f(rows[r-1][x], rows[r][x], rows[r+1][x]);
                    if (x > 0)
                        m = fmaxf(m, max3f(rows[r-1][x-1], rows[r][x-1], rows[r+1][x-1]));
                    if (x < WID - 1)
                        m = fmaxf(m, max3f(rows[r-1][x+1], rows[r][x+1], rows[r+1][x+1]));
                    ok = (v >= m);
                }
                unsigned ballot = __ballot_sync(0xffffffffu, ok);
                if (ok) {
                    int leader = __ffs(ballot) - 1;
                    int base = 0;
                    if (lane == leader) base = atomicAdd(&s_cnt, __popc(ballot));
                    base = __shfl_sync(ballot, base, leader);
                    int slot = base + __popc(ballot & ((1u << lane) - 1u));
                    if (slot < STAGE_MAX)
                        stage[slot] = mkkey(v, (unsigned)((y0 - 1 + r) * WID + x));
                }
            }
        }
        __syncthreads();

        int cnt = s_cnt; if (cnt > STAGE_MAX) cnt = STAGE_MAX;
        if (x == 0) s_base = atomicAdd(&g_cnt[img], cnt);
        __syncthreads();
        int base = s_base;
        for (int i = x; i < cnt; i += WID) {
            int slot = base + i;
            if (slot < SURV) g_cand[img][slot] = stage[i];
        }
    } else {
        // ---- gt collect path ----
        int blk = blockIdx.x - NMS_BLOCKS;
        int img = blk >> 4, sl = blk & (GSL - 1);
        const float4* hm4 = reinterpret_cast<const float4*>(gt_hm + (size_t)img * HW)
                          + sl * SLPX4;
        int pix0 = (sl * SLPX4) * 4;
        #pragma unroll
        for (int i = x; i < SLPX4; i += WID) {
            float4 v4 = __ldg(&hm4[i]);
            float vv[4] = {v4.x, v4.y, v4.z, v4.w};
            #pragma unroll
            for (int comp = 0; comp < 4; comp++) {
                bool keep = (vv[comp] >= TAU_G);
                wappend_g(keep, keep ? mkkey(vv[comp], (unsigned)(pix0 + 4*i + comp)) : 0,
                          &g_gtcnt[img], g_gtkeys[img], SURV);
            }
        }
    }
}

// ---------------------------------------------------------------------------
// SORT kernel: one CTA per output image. img < NB = pred, img >= NB = gt.
// Fast path (expected always): 500 <= cnt <= 1024 -> the exact top-500 is a
// subset of the collected survivors; pure bitonic sort, no histogram.
// Fallback (statistically never; exactness insurance): recompute candidates
// from the heatmap with the histogram+prune method.
__global__ void __launch_bounds__(1024) k_sort(const float* __restrict__ pred_hm,
                                               const float* __restrict__ gt_hm) {
    __shared__ unsigned long long keys[SURV];   // 8 KB
    __shared__ int hist[BINS];                  // 16 KB (fallback only)
    __shared__ int psum[1024];
    __shared__ int wsuf[32];
    __shared__ int s_bstar, s_nsurv;

    int img = blockIdx.x;
    int tid = threadIdx.x;
    bool is_gt = (img >= NB);
    int b = is_gt ? (img - NB) : img;
    int cnt = is_gt ? g_gtcnt[b] : g_cnt[b];
    const unsigned long long* list = is_gt ? g_gtkeys[b] : g_cand[b];

    if (cnt >= KTOP && cnt <= SURV) {
        keys[tid] = (tid < cnt) ? list[tid] : 0xFFFFFFFFFFFFFFFFULL;
        __syncthreads();
    } else {
        // ---- exact fallback: histogram + prune from the heatmap ----
        const float* hm = (is_gt ? gt_hm : pred_hm) + (size_t)b * HW;
        for (int i = tid; i < BINS; i += 1024) hist[i] = 0;
        if (tid == 0) { s_bstar = 0; s_nsurv = 0; }
        __syncthreads();
        for (int i = tid; i < HW; i += 1024) {
            float v = __ldg(&hm[i]);
            bool ok = is_gt ? true : nms_ok_g(hm, i >> 8, i & (WID - 1), v);
            if (ok) atomicAdd(&hist[val_bin(v)], 1);
        }
        __syncthreads();
        int bstar = compute_bstar(hist, psum, wsuf, &s_bstar, tid);
        for (int i = tid; i < HW; i += 1024) {
            float v = __ldg(&hm[i]);
            bool ok = (val_bin(v) >= bstar)
                   && (is_gt ? true : nms_ok_g(hm, i >> 8, i & (WID - 1), v));
            wappend_g(ok, ok ? mkkey(v, (unsigned)i) : 0, &s_nsurv, nullptr, 0);
            // (wappend_g writes via buf; use local variant below instead)
            if (ok) {
                // direct smem append (second ballot inside wappend_g unused here)
            }
        }
        // NOTE: rewrite of collect loop with smem append:
        if (tid == 0) s_nsurv = 0;
        __syncthreads();
        for (int i = tid; i < HW; i += 1024) {
            float v = __ldg(&hm[i]);
            bool ok = (val_bin(v) >= bstar)
                   && (is_gt ? true : nms_ok_g(hm, i >> 8, i & (WID - 1), v));
            int lane = tid & 31;
            unsigned ballot = __ballot_sync(0xffffffffu, ok);
            if (ok) {
                int leader = __ffs(ballot) - 1;
                int base2 = 0;
                if (lane == leader) base2 = atomicAdd(&s_nsurv, __popc(ballot));
                base2 = __shfl_sync(ballot, base2, leader);
                int slot = base2 + __popc(ballot & ((1u << lane) - 1u));
                if (slot < SURV) keys[slot] = mkkey(v, (unsigned)i);
            }
        }
        __syncthreads();
        int ns = s_nsurv; if (ns > SURV) ns = SURV;
        if (tid >= ns) keys[tid] = 0xFFFFFFFFFFFFFFFFULL;
        __syncthreads();
    }

    bitonic1024(keys, tid);

    if (tid < KTOP) {
        unsigned p = (unsigned)(keys[tid] & 0xFFFFFFFFULL);
        g_xs[img][tid] = (float)(p & (WID - 1));
        g_ys[img][tid] = (float)(p >> 8);
    }
    // reset consumed counters for next graph replay
    if (tid == 0) { if (is_gt) g_gtcnt[b] = 0; else g_cnt[b] = 0; }
}

// ---------------------------------------------------------------------------
// Loss (R8 version, measured 9.86us): one thread per (item, coordinate);
// mask gates the gathers.
#define LOSS_TPB 1024
#define LOSS_N   (NB * KTOP * 10)
__global__ void __launch_bounds__(LOSS_TPB)
k_loss(const float* __restrict__ pred_wh, const float* __restrict__ pred_reg,
       const float* __restrict__ pred_cls,
       const float* __restrict__ gt_wh, const float* __restrict__ gt_reg,
       const float* __restrict__ gt_cls,
       const int* __restrict__ gt_ind, const int* __restrict__ gt_mask,
       float* __restrict__ out) {
    int gidx = blockIdx.x * LOSS_TPB + threadIdx.x;
    float lsum = 0.f;
    int lcnt = 0;
    if (gidx < LOSS_N) {
        int t = gidx / 10;
        int c = gidx - t * 10;
        if (__ldg(&gt_mask[t]) != 0) {
            lcnt = 1;
            int b = t / KTOP;
            int k = t - b * KTOP;
            int ind = __ldg(&gt_ind[t]);
            bool odd = (c & 1);
            int iA = c_whA[c], iB = c_whB[c];
            float sg = c_sgn[c];
            float base, gbase;
            if (odd) {
                base  = g_ys[b][k]      + __ldg(&pred_reg[(size_t)(b * 2 + 1) * HW + ind]);
                gbase = g_ys[NB + b][k] + __ldg(&gt_reg[2 * t + 1]);
            } else {
                base  = g_xs[b][k]      + __ldg(&pred_reg[(size_t)(b * 2) * HW + ind]);
                gbase = g_xs[NB + b][k] + __ldg(&gt_reg[2 * t]);
            }
            bool m  = __ldg(&pred_cls[(size_t)b * HW + ind]) > 0.8f;
            bool gm = __ldg(&gt_cls[t]) > 0.8f;
            float pp = base, tt = gbase;
            // m exactly 0/1 in reference => branch == blend bit-exactly
            if (m) { if (iA >= 0) pp += __ldg(&pred_wh[((size_t)b * 10 + iA) * HW + ind]); }
            else   { if (iB >= 0) pp += sg * __ldg(&pred_wh[((size_t)b * 10 + iB) * HW + ind]); }
            if (gm) { if (iA >= 0) tt += __ldg(&gt_wh[10 * t + iA]); }
            else    { if (iB >= 0) tt += sg * __ldg(&gt_wh[10 * t + iB]); }
            float d = fabsf(pp - tt);
            lsum = (d < 1.f) ? 0.5f * d * d : (d - 0.5f);
        }
    }
    #pragma unroll
    for (int off = 16; off > 0; off >>= 1) {
        lsum += __shfl_down_sync(0xffffffffu, lsum, off);
        lcnt += __shfl_down_sync(0xffffffffu, lcnt, off);
    }
    __shared__ float wsum[LOSS_TPB / 32];
    __shared__ int   wcnt[LOSS_TPB / 32];
    int warp = threadIdx.x >> 5, lane = threadIdx.x & 31;
    if (lane == 0) { wsum[warp] = lsum; wcnt[warp] = lcnt; }
    __syncthreads();
    if (warp == 0) {
        float s = (lane < LOSS_TPB / 32) ? wsum[lane] : 0.f;
        int   cc = (lane < LOSS_TPB / 32) ? wcnt[lane] : 0;
        #pragma unroll
        for (int off = 16; off > 0; off >>= 1) {
            s  += __shfl_down_sync(0xffffffffu, s, off);
            cc += __shfl_down_sync(0xffffffffu, cc, off);
        }
        if (lane == 0) {
            atomicAdd(&g_sum, (double)s);
            atomicAdd(&g_tot, cc);
            __threadfence();
            unsigned ticket = atomicAdd(&g_ticket, 1u);
            if (ticket == gridDim.x - 1) {   // last block: finalize + reset
                double fs = g_sum;
                int tot = g_tot;
                float loss = 0.f;
                if (tot > 0) loss = (float)(fs / (double)(tot < 1 ? 1 : tot));
                out[0] = loss;
                g_sum = 0.0; g_tot = 0; g_ticket = 0u;
            }
        }
    }
}

// ---------------------------------------------------------------------------
extern "C" void kernel_launch(void* const* d_in, const int* in_sizes, int n_in,
                              void* d_out, int out_size) {
    const float* pred_hm  = (const float*)d_in[0];
    const float* pred_wh  = (const float*)d_in[1];
    const float* pred_reg = (const float*)d_in[2];
    const float* pred_cls = (const float*)d_in[3];
    const float* gt_hm    = (const float*)d_in[4];
    const float* gt_wh    = (const float*)d_in[5];
    const float* gt_reg   = (const float*)d_in[6];
    const float* gt_cls   = (const float*)d_in[7];
    const int*   gt_ind   = (const int*)d_in[8];
    const int*   gt_mask  = (const int*)d_in[9];
    float* out = (float*)d_out;

    k_scan<<<NMS_BLOCKS + GT_BLOCKS, WID>>>(pred_hm, gt_hm);
    k_sort<<<NIMG, 1024>>>(pred_hm, gt_hm);
    k_loss<<<(LOSS_N + LOSS_TPB - 1) / LOSS_TPB, LOSS_TPB>>>(
        pred_wh, pred_reg, pred_cls, gt_wh, gt_reg, gt_cls, gt_ind, gt_mask, out);
}